// round 4
// baseline (speedup 1.0000x reference)
#include <cuda_runtime.h>
#include <math.h>

// Accurate libdevice sine (1-2 ulp). Rounds 1-2 proved this declaration
// compiles, links, and is deterministic on this harness.
extern "C" __device__ float __nv_sinf(float);

#define T_LEN 480000
#define B_ROWS 64

// RN(1/16000): XLA's algebraic simplifier rewrites x/16000 -> x * (1/16000)
// with the reciprocal folded at compile time. Reproduce that EXACTLY: this
// is the ~1.8e-7-relative perturbation of the sin argument that explains the
// 4e-3 rel_err of rounds 1-3 (which used correctly-rounded division).
#define INV_SR 6.25e-5f

__global__ __launch_bounds__(256)
void chorus_kernel(const float* __restrict__ audio,
                   const float* __restrict__ rate_hz,
                   const float* __restrict__ depth,
                   const float* __restrict__ centre_ms,
                   const float* __restrict__ mix,
                   float* __restrict__ out)
{
    __shared__ float s_w[B_ROWS];     // f32(2*pi) * rate, ref op order
    __shared__ float s_dep[B_ROWS];
    __shared__ float s_cds[B_ROWS];   // centre_ms * 16
    __shared__ float s_mix[B_ROWS];

    const float TWO_PI_F = 6.28318530717958647692f;  // f32 = 0x40C90FDB
    if (threadIdx.x < B_ROWS) {
        const int b = threadIdx.x;
        s_w[b]   = __fmul_rn(TWO_PI_F, __ldg(rate_hz + b));
        s_dep[b] = __ldg(depth + b);
        s_cds[b] = __fmul_rn(__ldg(centre_ms + b), 16.0f);
        s_mix[b] = __ldg(mix + b);
    }
    __syncthreads();

    const int i = blockIdx.x * blockDim.x + threadIdx.x;
    if (i >= T_LEN) return;

    const float posf = (float)i;                     // exact (i < 2^24)
    // t = i * (1/16000)  -- multiply-by-reciprocal, as XLA computes it.
    const float t = __fmul_rn(posf, INV_SR);

    #pragma unroll 4
    for (int b = 0; b < B_ROWS; ++b) {
        // arg = ((2*pi)*rate) * t -- exact reference f32 op order, no FMA.
        const float arg = __fmul_rn(s_w[b], t);
        const float lfo = __nv_sinf(arg);

        const float cds = s_cds[b];
        // delay = cds + ((lfo*depth)*cds), un-contracted, clip [1, 800].
        float delay = __fadd_rn(cds, __fmul_rn(__fmul_rn(lfo, s_dep[b]), cds));
        delay = fminf(fmaxf(delay, 1.0f), 800.0f);

        // read_pos quantized at ulp(pos) ~ 0.03 -- reproduce ref's f32 sub.
        const float rp   = __fsub_rn(posf, delay);
        const float lowf = floorf(rp);
        const float frac = __fsub_rn(rp, lowf);

        // delay >= 1 -> rp <= pos-1 -> lowf <= L-2; ref's upper clip dead.
        const int il = (int)fmaxf(lowf, 0.0f);

        const float* row = audio + (size_t)b * T_LEN;
        const float a0 = __ldg(row + il);
        const float a1 = __ldg(row + il + 1);
        const float x  = __ldg(row + i);

        const float delayed = (rp >= 0.0f)
            ? (a0 * (1.0f - frac) + a1 * frac)
            : 0.0f;

        const float mx = s_mix[b];
        out[(size_t)b * T_LEN + i] = x * (1.0f - mx) + delayed * mx;
    }
}

extern "C" void kernel_launch(void* const* d_in, const int* in_sizes, int n_in,
                              void* d_out, int out_size)
{
    // metadata order: audio, rate_hz, depth, centre_delay_ms, feedback(unused), mix
    const float* audio     = (const float*)d_in[0];
    const float* rate_hz   = (const float*)d_in[1];
    const float* depth     = (const float*)d_in[2];
    const float* centre_ms = (const float*)d_in[3];
    const float* mix       = (const float*)d_in[5];
    float* out = (float*)d_out;

    (void)in_sizes; (void)n_in; (void)out_size;

    const int threads = 256;
    const int blocks  = (T_LEN + threads - 1) / threads;
    chorus_kernel<<<blocks, threads>>>(audio, rate_hz, depth, centre_ms, mix, out);
}

// round 5
// speedup vs baseline: 1.2931x; 1.2931x over previous
#include <cuda_runtime.h>
#include <math.h>

#define T_LEN 480000
#define B_ROWS 64

// RN(1/16000): matches XLA's divide->multiply-by-reciprocal rewrite (round-4
// win; load-bearing for correctness, do not change).
#define INV_SR 6.25e-5f

// ---------------------------------------------------------------------------
// Branch-free accurate sine, flag-immune (all explicit _rn intrinsics).
// Valid for 0 <= x <= 424 here (n <= 272 << 2^22, Cody-Waite exact).
// Abs error ~1.5e-7; field-tested round 2 (tracked libdevice to ~1e-6).
// ~16 instructions vs ~25 for libdevice __nv_sinf (no range branches, no
// Payne-Hanek guard, no slow-path code).
// ---------------------------------------------------------------------------
__device__ __forceinline__ float sin_acc(float x)
{
    const float MAGIC = 12582912.0f;                  // 1.5 * 2^23
    float jf = __fmaf_rn(x, 0.636619747f, MAGIC);     // round(x * 2/pi)
    int   q  = __float_as_int(jf);                    // low bits = quadrant
    float n  = __fsub_rn(jf, MAGIC);

    float r = __fmaf_rn(n, -1.57079601287841796875e+00f, x);
    r = __fmaf_rn(n, -3.13916473738675476075e-07f, r);
    r = __fmaf_rn(n, -5.39030252995776476554e-15f, r);

    float s2 = __fmul_rn(r, r);

    // sin core
    float u = __fmaf_rn(-1.9515295891e-4f, s2,  8.3321608736e-3f);
    u = __fmaf_rn(u, s2, -1.6666654611e-1f);
    float sinr = __fmaf_rn(__fmul_rn(u, s2), r, r);

    // cos core
    float v = __fmaf_rn(2.443315711809948e-5f, s2, -1.388731625493765e-3f);
    v = __fmaf_rn(v, s2, 4.166664568298827e-2f);
    float cosr = __fmaf_rn(__fmul_rn(v, s2), s2, __fmaf_rn(-0.5f, s2, 1.0f));

    float res = (q & 1) ? cosr : sinr;
    unsigned sgn = ((unsigned)q & 2u) << 30;          // quadrant sign flip
    return __int_as_float(__float_as_int(res) ^ (int)sgn);
}

__global__ __launch_bounds__(256)
void chorus_kernel(const float* __restrict__ audio,
                   const float* __restrict__ rate_hz,
                   const float* __restrict__ depth,
                   const float* __restrict__ centre_ms,
                   const float* __restrict__ mix,
                   float* __restrict__ out)
{
    __shared__ float s_w[B_ROWS];     // f32(2*pi) * rate, ref op order
    __shared__ float s_dep[B_ROWS];
    __shared__ float s_cds[B_ROWS];   // centre_ms * 16
    __shared__ float s_mix[B_ROWS];

    const float TWO_PI_F = 6.28318530717958647692f;   // f32 = 0x40C90FDB
    if (threadIdx.x < B_ROWS) {
        const int b = threadIdx.x;
        s_w[b]   = __fmul_rn(TWO_PI_F, __ldg(rate_hz + b));
        s_dep[b] = __ldg(depth + b);
        s_cds[b] = __fmul_rn(__ldg(centre_ms + b), 16.0f);
        s_mix[b] = __ldg(mix + b);
    }
    __syncthreads();

    const int i = blockIdx.x * blockDim.x + threadIdx.x;
    if (i >= T_LEN) return;

    const float posf = (float)i;                      // exact (i < 2^24)
    const float t = __fmul_rn(posf, INV_SR);          // XLA reciprocal-mul

    const float* __restrict__ row = audio;
    float* __restrict__ orow = out;

    #pragma unroll 8
    for (int b = 0; b < B_ROWS; ++b, row += T_LEN, orow += T_LEN) {
        // arg = ((2*pi)*rate) * t -- exact reference f32 op order, no FMA.
        const float arg = __fmul_rn(s_w[b], t);
        const float lfo = sin_acc(arg);

        const float cds = s_cds[b];
        float delay = __fadd_rn(cds, __fmul_rn(__fmul_rn(lfo, s_dep[b]), cds));
        delay = fminf(fmaxf(delay, 1.0f), 800.0f);

        // read_pos in f32 exactly like ref; quantized at ulp(pos) ~ 0.03.
        const float rp = __fsub_rn(posf, delay);
        // floor + int-convert in one instruction (round toward -inf); clamp
        // below at 0 (delay >= 1 -> il <= i-1 <= L-2 always, upper clip dead).
        int il = __float2int_rd(rp);
        il = max(il, 0);
        const float frac = __fsub_rn(rp, floorf(rp));

        const float a0 = __ldg(row + il);
        const float a1 = __ldg(row + il + 1);
        const float x  = __ldg(row + i);

        // a0*(1-frac) + a1*frac == a0 + frac*(a1-a0) up to 1 ulp (continuous
        // path, 1e-3 budget): 2 ops instead of 3.
        float delayed = __fmaf_rn(frac, __fsub_rn(a1, a0), a0);
        delayed = (rp >= 0.0f) ? delayed : 0.0f;

        const float mx = s_mix[b];
        orow[i] = x * (1.0f - mx) + delayed * mx;
    }
}

extern "C" void kernel_launch(void* const* d_in, const int* in_sizes, int n_in,
                              void* d_out, int out_size)
{
    // metadata order: audio, rate_hz, depth, centre_delay_ms, feedback(unused), mix
    const float* audio     = (const float*)d_in[0];
    const float* rate_hz   = (const float*)d_in[1];
    const float* depth     = (const float*)d_in[2];
    const float* centre_ms = (const float*)d_in[3];
    const float* mix       = (const float*)d_in[5];
    float* out = (float*)d_out;

    (void)in_sizes; (void)n_in; (void)out_size;

    const int threads = 256;
    const int blocks  = (T_LEN + threads - 1) / threads;
    chorus_kernel<<<blocks, threads>>>(audio, rate_hz, depth, centre_ms, mix, out);
}